// round 16
// baseline (speedup 1.0000x reference)
#include <cuda_runtime.h>
#include <cuda_fp16.h>
#include <mma.h>
#include <cstdint>
#include <math.h>

using namespace nvcuda;

#define Dm 512
#define Tt 2048
#define Bb 4
#define BT 8192
#define FFd 2048
#define Ee 4
#define MAXTOK 8192
#define NCHUNK 16

// ---- split GEMM (128x128 tile, BK=32, 3-stage, 512 thr) smem layout (halves) ----
#define ALDH 40
#define SBLDH 136
#define SCLD  132
#define A_STG (128 * ALDH)          // 5120
#define SB_STG (32 * SBLDH)         // 4352
#define ALB  (3 * A_STG)            // 15360
#define BHB  (6 * A_STG)            // 30720
#define BLB  (BHB + 3 * SB_STG)     // 43776
#define S_SMEM_BYTES ((BLB + 3 * SB_STG) * 2)   // 113664 B

// ---- MoE GEMM (128x128 tile, BK=32, 3-stage, 256 thr) smem layout ----
#define MALDH 40
#define MBLDH 136
#define MCLD  136
#define MA_STG (128 * MALDH)        // 5120
#define MB_STG (32 * MBLDH)         // 4352
#define MBHB (3 * MA_STG)           // 15360
#define M_SMEM_BYTES (128 * MCLD * 4)  // 69632 B

// ---------------- scratch ----------------
__device__ float  g_K[BT * Dm];
__device__ float  g_V[BT * Dm];
__device__ float  g_tmp[BT * Dm];
__device__ float  g_x1[BT * Dm];
__device__ float  g_part[Bb * NCHUNK * Dm];
__device__ float  g_kvsum[Bb * Dm];
__device__ int    g_counts[Ee];
__device__ int    g_tok[Ee * MAXTOK];
__device__ float  g_wslot[Ee * MAXTOK];
__device__ int    g_slottok[BT * 2];
__device__ float  g_ybuf[(size_t)Ee * MAXTOK * Dm];
// half operand buffers
__device__ __half g_xh[BT * Dm],  g_xl[BT * Dm];
__device__ __half g_Wkh[Dm * Dm], g_Wkl[Dm * Dm];
__device__ __half g_Wvh[Dm * Dm], g_Wvl[Dm * Dm];
__device__ __half g_Woh[Dm * Dm], g_Wol[Dm * Dm];
__device__ __half g_fbh[(size_t)Bb * Tt * Tt], g_fbl[(size_t)Bb * Tt * Tt];
__device__ __half g_Vh[BT * Dm],  g_Vl[BT * Dm];
__device__ __half g_wvh[BT * Dm], g_wvl[BT * Dm];
__device__ __half g_x1h[BT * Dm];
__device__ __half g_W1h[(size_t)Ee * Dm * FFd];
__device__ __half g_W2h[(size_t)Ee * FFd * Dm];
__device__ __half g_hh[(size_t)Ee * MAXTOK * FFd];

// ---------------- cp.async helpers ----------------
__device__ __forceinline__ void cp_async16(uint32_t saddr, const void* gptr) {
    asm volatile("cp.async.cg.shared.global [%0], [%1], 16;" :: "r"(saddr), "l"(gptr));
}
#define CP_COMMIT() asm volatile("cp.async.commit_group;")
#define CP_WAIT(n)  asm volatile("cp.async.wait_group %0;" :: "n"(n))

// ---------------- small kernels ----------------
__global__ void zero_counts_kernel() {
    if (threadIdx.x < Ee) g_counts[threadIdx.x] = 0;
}
__global__ void kvsum_partial_kernel() {
    int b = blockIdx.y, tc = blockIdx.x, d = threadIdx.x;
    const float* Kp = g_K + ((long long)b * Tt + (long long)tc * (Tt / NCHUNK)) * Dm;
    const float* Vp = g_V + ((long long)b * Tt + (long long)tc * (Tt / NCHUNK)) * Dm;
    float s = 0.f;
#pragma unroll 8
    for (int t = 0; t < Tt / NCHUNK; ++t)
        s += Kp[(long long)t * Dm + d] * Vp[(long long)t * Dm + d];
    g_part[((long long)b * NCHUNK + tc) * Dm + d] = s;
}
__global__ void kvsum_reduce_kernel() {
    int i = blockIdx.x * 256 + threadIdx.x;
    int b = i >> 9;
    float s = 0.f;
    for (int tc = 0; tc < NCHUNK; ++tc)
        s += g_part[((long long)b * NCHUNK + tc) * Dm + (i & 511)];
    g_kvsum[i] = s;
}
__global__ void split_half_kernel(const float* __restrict__ in, __half* __restrict__ h,
                                  __half* __restrict__ l, long long n4) {
    long long i = (long long)blockIdx.x * 256 + threadIdx.x;
    long long stride = (long long)gridDim.x * 256;
    for (; i < n4; i += stride) {
        float4 v = reinterpret_cast<const float4*>(in)[i];
        __half h0 = __float2half_rn(v.x), h1 = __float2half_rn(v.y);
        __half h2 = __float2half_rn(v.z), h3 = __float2half_rn(v.w);
        __half l0 = __float2half_rn(v.x - __half2float(h0));
        __half l1 = __float2half_rn(v.y - __half2float(h1));
        __half l2 = __float2half_rn(v.z - __half2float(h2));
        __half l3 = __float2half_rn(v.w - __half2float(h3));
        reinterpret_cast<__half2*>(h)[2 * i]     = __halves2half2(h0, h1);
        reinterpret_cast<__half2*>(h)[2 * i + 1] = __halves2half2(h2, h3);
        reinterpret_cast<__half2*>(l)[2 * i]     = __halves2half2(l0, l1);
        reinterpret_cast<__half2*>(l)[2 * i + 1] = __halves2half2(l2, l3);
    }
}
__global__ void tohalf_kernel(const float* __restrict__ in, __half* __restrict__ h, long long n4) {
    long long i = (long long)blockIdx.x * 256 + threadIdx.x;
    long long stride = (long long)gridDim.x * 256;
    for (; i < n4; i += stride) {
        float4 v = reinterpret_cast<const float4*>(in)[i];
        reinterpret_cast<__half2*>(h)[2 * i]     = __halves2half2(__float2half_rn(v.x), __float2half_rn(v.y));
        reinterpret_cast<__half2*>(h)[2 * i + 1] = __halves2half2(__float2half_rn(v.z), __float2half_rn(v.w));
    }
}

// ---------------- split fp16 GEMM (128x128, BK=32, 3-stage, 512 threads) ----------------
// MODE 0: fp32 out (K-proj, Wo); MODE 3: fp32 + half-split out (V); MODE 4: half-split out (fbV)
template<int MODE>
__global__ __launch_bounds__(512, 1)
void gemm_split(const __half* __restrict__ Ahg, const __half* __restrict__ Alg,
                const __half* __restrict__ Bhg, const __half* __restrict__ Blg,
                const float* __restrict__ bias,
                float* __restrict__ Cf, __half* __restrict__ Chh, __half* __restrict__ Chl,
                int M, int N, int K,
                long long sA, long long sB, long long sBias, long long sC)
{
    extern __shared__ __half smh[];
    const int z = blockIdx.z;
    const int row0 = blockIdx.y * 128;
    const int col0 = blockIdx.x * 128;
    Ahg += (long long)z * sA;  Alg += (long long)z * sA;
    Bhg += (long long)z * sB;  Blg += (long long)z * sB;
    const float* bz = bias + (long long)z * sBias;
    const long long coff = (long long)z * sC;

    const int tid = threadIdx.x;
    const int warpId = tid >> 5;
    const int warpM = warpId >> 2;   // 0..3, 32 rows
    const int warpN = warpId & 3;    // 0..3, 32 cols

    const uint32_t sbase = (uint32_t)__cvta_generic_to_shared(smh);

    // A: 128x32 halves = 512 16B chunks -> 1/thread; B: 32x128 = 512 chunks -> 1/thread
    const int aRr = tid >> 2, aC8 = (tid & 3) * 8;
    const int bRr = tid >> 4, bC8 = (tid & 15) * 8;

#define LOAD_TILE(stage, kk)                                                      \
    do {                                                                          \
        cp_async16(sbase + ((stage) * A_STG + aRr * ALDH + aC8) * 2,              \
                   Ahg + (long long)(row0 + aRr) * K + (kk) + aC8);               \
        cp_async16(sbase + (ALB + (stage) * A_STG + aRr * ALDH + aC8) * 2,        \
                   Alg + (long long)(row0 + aRr) * K + (kk) + aC8);               \
        cp_async16(sbase + (BHB + (stage) * SB_STG + bRr * SBLDH + bC8) * 2,      \
                   Bhg + (long long)((kk) + bRr) * N + col0 + bC8);               \
        cp_async16(sbase + (BLB + (stage) * SB_STG + bRr * SBLDH + bC8) * 2,      \
                   Blg + (long long)((kk) + bRr) * N + col0 + bC8);               \
    } while (0)

    wmma::fragment<wmma::accumulator, 16, 16, 16, float> acc[2][2];
#pragma unroll
    for (int i = 0; i < 2; i++)
#pragma unroll
        for (int j = 0; j < 2; j++) wmma::fill_fragment(acc[i][j], 0.f);

    const int nk = K >> 5;
    LOAD_TILE(0, 0); CP_COMMIT();
    LOAD_TILE(1, 32); CP_COMMIT();

    int s = 0;
    for (int t = 0; t < nk; ++t) {
        if (t + 2 < nk) {
            int s2 = s + 2; if (s2 >= 3) s2 -= 3;
            LOAD_TILE(s2, (t + 2) * 32);
            CP_COMMIT();
            CP_WAIT(2);
        } else if (t + 1 < nk) {
            CP_WAIT(1);
        } else {
            CP_WAIT(0);
        }
        __syncthreads();

        const __half* As_h = smh + s * A_STG;
        const __half* As_l = smh + ALB + s * A_STG;
        const __half* Bs_h = smh + BHB + s * SB_STG;
        const __half* Bs_l = smh + BLB + s * SB_STG;
#pragma unroll
        for (int ks = 0; ks < 2; ks++) {
            wmma::fragment<wmma::matrix_a, 16, 16, 16, __half, wmma::row_major> ah[2], al[2];
#pragma unroll
            for (int i = 0; i < 2; i++) {
                wmma::load_matrix_sync(ah[i], As_h + (warpM * 32 + i * 16) * ALDH + ks * 16, ALDH);
                wmma::load_matrix_sync(al[i], As_l + (warpM * 32 + i * 16) * ALDH + ks * 16, ALDH);
            }
#pragma unroll
            for (int j = 0; j < 2; j++) {
                wmma::fragment<wmma::matrix_b, 16, 16, 16, __half, wmma::row_major> bh, bl;
                wmma::load_matrix_sync(bh, Bs_h + (ks * 16) * SBLDH + warpN * 32 + j * 16, SBLDH);
                wmma::load_matrix_sync(bl, Bs_l + (ks * 16) * SBLDH + warpN * 32 + j * 16, SBLDH);
#pragma unroll
                for (int i = 0; i < 2; i++) {
                    wmma::mma_sync(acc[i][j], ah[i], bh, acc[i][j]);
                    wmma::mma_sync(acc[i][j], ah[i], bl, acc[i][j]);
                    wmma::mma_sync(acc[i][j], al[i], bh, acc[i][j]);
                }
            }
        }
        __syncthreads();
        s = (s == 2) ? 0 : s + 1;
    }
#undef LOAD_TILE

    float* Cbuf = reinterpret_cast<float*>(smh);
#pragma unroll
    for (int i = 0; i < 2; i++)
#pragma unroll
        for (int j = 0; j < 2; j++)
            wmma::store_matrix_sync(Cbuf + (warpM * 32 + i * 16) * SCLD + warpN * 32 + j * 16,
                                    acc[i][j], SCLD, wmma::mem_row_major);
    __syncthreads();

#pragma unroll
    for (int it = 0; it < 8; it++) {
        int f = tid + it * 512;          // 4096 float4 chunks
        int r = f >> 5, c4 = f & 31;
        int grow = row0 + r;
        float4 v = *reinterpret_cast<const float4*>(Cbuf + r * SCLD + c4 * 4);
        int col = col0 + c4 * 4;
        v.x += __ldg(bz + col + 0);
        v.y += __ldg(bz + col + 1);
        v.z += __ldg(bz + col + 2);
        v.w += __ldg(bz + col + 3);
        long long idx = coff + (long long)grow * N + col;
        if (MODE == 0 || MODE == 3) *reinterpret_cast<float4*>(Cf + idx) = v;
        if (MODE == 3 || MODE == 4) {
            __half h0 = __float2half_rn(v.x), h1 = __float2half_rn(v.y);
            __half h2 = __float2half_rn(v.z), h3 = __float2half_rn(v.w);
            *reinterpret_cast<__half2*>(Chh + idx)     = __halves2half2(h0, h1);
            *reinterpret_cast<__half2*>(Chh + idx + 2) = __halves2half2(h2, h3);
            *reinterpret_cast<__half2*>(Chl + idx)     = __halves2half2(
                __float2half_rn(v.x - __half2float(h0)), __float2half_rn(v.y - __half2float(h1)));
            *reinterpret_cast<__half2*>(Chl + idx + 2) = __halves2half2(
                __float2half_rn(v.z - __half2float(h2)), __float2half_rn(v.w - __half2float(h3)));
        }
    }
}

// ---------------- MoE fp16 GEMM (128x128, BK=32, 3-stage, 256 threads) ----------------
// MODE 1: gather A rows via g_tok + relu + half out; MODE 2: row-scale g_wslot + fp32 out
template<int MODE>
__global__ __launch_bounds__(256, 2)
void gemm_moe(const __half* __restrict__ Ag, const __half* __restrict__ Bg,
              const float* __restrict__ bias,
              float* __restrict__ Cf, __half* __restrict__ Ch,
              int M, int N, int K,
              long long sA, long long sB, long long sBias, long long sC)
{
    extern __shared__ __half smh[];
    const int z = blockIdx.z;
    const int cnt = g_counts[z];
    const int row0 = blockIdx.y * 128;
    if (row0 >= cnt) return;
    const int col0 = blockIdx.x * 128;
    Ag += (long long)z * sA;
    Bg += (long long)z * sB;
    const float* bz = bias + (long long)z * sBias;
    const long long coff = (long long)z * sC;

    const int tid = threadIdx.x;
    const int warpId = tid >> 5;
    const int warpM = warpId >> 1;   // 0..3, 32 rows
    const int warpN = warpId & 1;    // 0..1, 64 cols

    __shared__ int toks[128];
    if (MODE == 1 && tid < 128) {
        int slot = row0 + tid;
        toks[tid] = (slot < cnt) ? g_tok[z * MAXTOK + slot] : g_tok[z * MAXTOK];
    }
    if (MODE == 1) __syncthreads();

    const uint32_t sbase = (uint32_t)__cvta_generic_to_shared(smh);

#define MLOAD(stage, kk)                                                          \
    do {                                                                          \
        _Pragma("unroll")                                                         \
        for (int p = 0; p < 2; p++) {                                             \
            int c = tid + p * 256;                                                \
            int r = c >> 2, c8 = (c & 3) * 8;                                     \
            int rowIdx = (MODE == 1) ? toks[r] : (row0 + r);                      \
            cp_async16(sbase + ((stage) * MA_STG + r * MALDH + c8) * 2,           \
                       Ag + (long long)rowIdx * K + (kk) + c8);                   \
        }                                                                         \
        _Pragma("unroll")                                                         \
        for (int p = 0; p < 2; p++) {                                             \
            int c = tid + p * 256;                                                \
            int r = c >> 4, c8 = (c & 15) * 8;                                    \
            cp_async16(sbase + (MBHB + (stage) * MB_STG + r * MBLDH + c8) * 2,    \
                       Bg + (long long)((kk) + r) * N + col0 + c8);               \
        }                                                                         \
    } while (0)

    wmma::fragment<wmma::accumulator, 16, 16, 16, float> acc[2][4];
#pragma unroll
    for (int i = 0; i < 2; i++)
#pragma unroll
        for (int j = 0; j < 4; j++) wmma::fill_fragment(acc[i][j], 0.f);

    const int nk = K >> 5;
    MLOAD(0, 0); CP_COMMIT();
    MLOAD(1, 32); CP_COMMIT();

    int s = 0;
    for (int t = 0; t < nk; ++t) {
        if (t + 2 < nk) {
            int s2 = s + 2; if (s2 >= 3) s2 -= 3;
            MLOAD(s2, (t + 2) * 32);
            CP_COMMIT();
            CP_WAIT(2);
        } else if (t + 1 < nk) {
            CP_WAIT(1);
        } else {
            CP_WAIT(0);
        }
        __syncthreads();

        const __half* As = smh + s * MA_STG;
        const __half* Bs = smh + MBHB + s * MB_STG;
#pragma unroll
        for (int ks = 0; ks < 2; ks++) {
            wmma::fragment<wmma::matrix_a, 16, 16, 16, __half, wmma::row_major> ah[2];
#pragma unroll
            for (int i = 0; i < 2; i++)
                wmma::load_matrix_sync(ah[i], As + (warpM * 32 + i * 16) * MALDH + ks * 16, MALDH);
#pragma unroll
            for (int j = 0; j < 4; j++) {
                wmma::fragment<wmma::matrix_b, 16, 16, 16, __half, wmma::row_major> bh;
                wmma::load_matrix_sync(bh, Bs + (ks * 16) * MBLDH + warpN * 64 + j * 16, MBLDH);
#pragma unroll
                for (int i = 0; i < 2; i++)
                    wmma::mma_sync(acc[i][j], ah[i], bh, acc[i][j]);
            }
        }
        __syncthreads();
        s = (s == 2) ? 0 : s + 1;
    }
#undef MLOAD

    float* Cbuf = reinterpret_cast<float*>(smh);
#pragma unroll
    for (int i = 0; i < 2; i++)
#pragma unroll
        for (int j = 0; j < 4; j++)
            wmma::store_matrix_sync(Cbuf + (warpM * 32 + i * 16) * MCLD + warpN * 64 + j * 16,
                                    acc[i][j], MCLD, wmma::mem_row_major);
    __syncthreads();

#pragma unroll
    for (int it = 0; it < 16; it++) {
        int f = tid + it * 256;          // 4096 float4 chunks
        int r = f >> 5, c4 = f & 31;
        int grow = row0 + r;
        if (grow >= cnt) continue;
        float4 v = *reinterpret_cast<const float4*>(Cbuf + r * MCLD + c4 * 4);
        int col = col0 + c4 * 4;
        v.x += __ldg(bz + col + 0);
        v.y += __ldg(bz + col + 1);
        v.z += __ldg(bz + col + 2);
        v.w += __ldg(bz + col + 3);
        long long idx = coff + (long long)grow * N + col;
        if (MODE == 1) {
            v.x = fmaxf(v.x, 0.f); v.y = fmaxf(v.y, 0.f);
            v.z = fmaxf(v.z, 0.f); v.w = fmaxf(v.w, 0.f);
            *reinterpret_cast<__half2*>(Ch + idx)     = __halves2half2(__float2half_rn(v.x), __float2half_rn(v.y));
            *reinterpret_cast<__half2*>(Ch + idx + 2) = __halves2half2(__float2half_rn(v.z), __float2half_rn(v.w));
        } else {
            float w = g_wslot[z * MAXTOK + grow];
            v.x *= w; v.y *= w; v.z *= w; v.w *= w;
            *reinterpret_cast<float4*>(Cf + idx) = v;
        }
    }
}

// ---------------- LN1: x1 = LN(x + tmp), also emit x1 as half ----------------
__global__ __launch_bounds__(256) void add_ln1_kernel(
    const float* __restrict__ x, const float* __restrict__ g, const float* __restrict__ b)
{
    int t = blockIdx.x, tid = threadIdx.x;
    const float* xr = x + (long long)t * Dm;
    const float* tr = g_tmp + (long long)t * Dm;
    float v0 = xr[tid] + tr[tid];
    float v1 = xr[tid + 256] + tr[tid + 256];
    __shared__ float red[256];
    red[tid] = v0 + v1;
    __syncthreads();
    for (int off = 128; off; off >>= 1) { if (tid < off) red[tid] += red[tid + off]; __syncthreads(); }
    float mu = red[0] * (1.0f / 512.0f);
    __syncthreads();
    float d0 = v0 - mu, d1 = v1 - mu;
    red[tid] = d0 * d0 + d1 * d1;
    __syncthreads();
    for (int off = 128; off; off >>= 1) { if (tid < off) red[tid] += red[tid + off]; __syncthreads(); }
    float inv = rsqrtf(red[0] * (1.0f / 512.0f) + 1e-5f);
    float o0 = d0 * inv * g[tid] + b[tid];
    float o1 = d1 * inv * g[tid + 256] + b[tid + 256];
    g_x1[(long long)t * Dm + tid]        = o0;
    g_x1[(long long)t * Dm + tid + 256]  = o1;
    g_x1h[(long long)t * Dm + tid]       = __float2half_rn(o0);
    g_x1h[(long long)t * Dm + tid + 256] = __float2half_rn(o1);
}

// ---------------- gate (exact fp32) ----------------
__global__ __launch_bounds__(128) void gate_kernel(
    const float* __restrict__ Wg, const float* __restrict__ bg)
{
    int t = blockIdx.x, tid = threadIdx.x;
    const float* xr = g_x1 + (long long)t * Dm;
    float p0 = 0, p1 = 0, p2 = 0, p3 = 0;
    const float4* Wg4 = reinterpret_cast<const float4*>(Wg);
    for (int d = tid; d < Dm; d += 128) {
        float xv = xr[d];
        float4 w = Wg4[d];
        p0 = fmaf(xv, w.x, p0); p1 = fmaf(xv, w.y, p1);
        p2 = fmaf(xv, w.z, p2); p3 = fmaf(xv, w.w, p3);
    }
    __shared__ float smr[4][128];
    smr[0][tid] = p0; smr[1][tid] = p1; smr[2][tid] = p2; smr[3][tid] = p3;
    __syncthreads();
    for (int off = 64; off; off >>= 1) {
        if (tid < off) {
            smr[0][tid] += smr[0][tid + off];
            smr[1][tid] += smr[1][tid + off];
            smr[2][tid] += smr[2][tid + off];
            smr[3][tid] += smr[3][tid + off];
        }
        __syncthreads();
    }
    if (tid == 0) {
        float s[4] = { smr[0][0] + bg[0], smr[1][0] + bg[1], smr[2][0] + bg[2], smr[3][0] + bg[3] };
        float m = fmaxf(fmaxf(s[0], s[1]), fmaxf(s[2], s[3]));
        float ex[4]; float sum = 0.f;
        for (int e = 0; e < 4; e++) { ex[e] = expf(s[e] - m); sum += ex[e]; }
        float invs = 1.0f / sum;
        float pr[4];
        for (int e = 0; e < 4; e++) pr[e] = ex[e] * invs;
        int i0 = 0;
        for (int e = 1; e < 4; e++) if (pr[e] > pr[i0]) i0 = e;
        int i1 = -1;
        for (int e = 0; e < 4; e++) {
            if (e == i0) continue;
            if (i1 < 0 || pr[e] > pr[i1]) i1 = e;
        }
        int s0 = atomicAdd(&g_counts[i0], 1);
        g_tok[i0 * MAXTOK + s0] = t;
        g_wslot[i0 * MAXTOK + s0] = pr[i0];
        g_slottok[2 * t] = i0 * MAXTOK + s0;
        int s1 = atomicAdd(&g_counts[i1], 1);
        g_tok[i1 * MAXTOK + s1] = t;
        g_wslot[i1 * MAXTOK + s1] = pr[i1];
        g_slottok[2 * t + 1] = i1 * MAXTOK + s1;
    }
}

// ---------------- combine + LN2 ----------------
__global__ __launch_bounds__(256) void combine_ln2_kernel(
    const float* __restrict__ g, const float* __restrict__ b, float* __restrict__ out)
{
    int t = blockIdx.x, tid = threadIdx.x;
    int s0 = g_slottok[2 * t], s1 = g_slottok[2 * t + 1];
    const float* xr = g_x1 + (long long)t * Dm;
    const float* y0 = g_ybuf + (long long)s0 * Dm;
    const float* y1 = g_ybuf + (long long)s1 * Dm;
    float v0 = xr[tid] + y0[tid] + y1[tid];
    float v1 = xr[tid + 256] + y0[tid + 256] + y1[tid + 256];
    __shared__ float red[256];
    red[tid] = v0 + v1;
    __syncthreads();
    for (int off = 128; off; off >>= 1) { if (tid < off) red[tid] += red[tid + off]; __syncthreads(); }
    float mu = red[0] * (1.0f / 512.0f);
    __syncthreads();
    float d0 = v0 - mu, d1 = v1 - mu;
    red[tid] = d0 * d0 + d1 * d1;
    __syncthreads();
    for (int off = 128; off; off >>= 1) { if (tid < off) red[tid] += red[tid + off]; __syncthreads(); }
    float inv = rsqrtf(red[0] * (1.0f / 512.0f) + 1e-5f);
    out[(long long)t * Dm + tid]       = d0 * inv * g[tid] + b[tid];
    out[(long long)t * Dm + tid + 256] = d1 * inv * g[tid + 256] + b[tid + 256];
}

// ---------------- launch ----------------
extern "C" void kernel_launch(void* const* d_in, const int* in_sizes, int n_in,
                              void* d_out, int out_size)
{
    const float* x    = (const float*)d_in[0];
    const float* fb   = (const float*)d_in[1];
    const float* Wk   = (const float*)d_in[2];
    const float* bk   = (const float*)d_in[3];
    const float* Wv   = (const float*)d_in[4];
    const float* bv   = (const float*)d_in[5];
    const float* Wo   = (const float*)d_in[6];
    const float* bo   = (const float*)d_in[7];
    const float* ln1g = (const float*)d_in[8];
    const float* ln1b = (const float*)d_in[9];
    const float* Wg   = (const float*)d_in[10];
    const float* bg   = (const float*)d_in[11];
    const float* W1   = (const float*)d_in[12];
    const float* b1   = (const float*)d_in[13];
    const float* W2   = (const float*)d_in[14];
    const float* b2   = (const float*)d_in[15];
    const float* ln2g = (const float*)d_in[16];
    const float* ln2b = (const float*)d_in[17];
    float* out = (float*)d_out;

    float *pK, *pV, *ptmp, *pkvs, *pyb;
    __half *pxh, *pxl, *pWkh, *pWkl, *pWvh, *pWvl, *pWoh, *pWol;
    __half *pfbh, *pfbl, *pVh, *pVl, *pwvh, *pwvl, *px1h, *pW1h, *pW2h, *phh;
    cudaGetSymbolAddress((void**)&pK,   g_K);
    cudaGetSymbolAddress((void**)&pV,   g_V);
    cudaGetSymbolAddress((void**)&ptmp, g_tmp);
    cudaGetSymbolAddress((void**)&pkvs, g_kvsum);
    cudaGetSymbolAddress((void**)&pyb,  g_ybuf);
    cudaGetSymbolAddress((void**)&pxh,  g_xh);
    cudaGetSymbolAddress((void**)&pxl,  g_xl);
    cudaGetSymbolAddress((void**)&pWkh, g_Wkh);
    cudaGetSymbolAddress((void**)&pWkl, g_Wkl);
    cudaGetSymbolAddress((void**)&pWvh, g_Wvh);
    cudaGetSymbolAddress((void**)&pWvl, g_Wvl);
    cudaGetSymbolAddress((void**)&pWoh, g_Woh);
    cudaGetSymbolAddress((void**)&pWol, g_Wol);
    cudaGetSymbolAddress((void**)&pfbh, g_fbh);
    cudaGetSymbolAddress((void**)&pfbl, g_fbl);
    cudaGetSymbolAddress((void**)&pVh,  g_Vh);
    cudaGetSymbolAddress((void**)&pVl,  g_Vl);
    cudaGetSymbolAddress((void**)&pwvh, g_wvh);
    cudaGetSymbolAddress((void**)&pwvl, g_wvl);
    cudaGetSymbolAddress((void**)&px1h, g_x1h);
    cudaGetSymbolAddress((void**)&pW1h, g_W1h);
    cudaGetSymbolAddress((void**)&pW2h, g_W2h);
    cudaGetSymbolAddress((void**)&phh,  g_hh);

    cudaFuncSetAttribute(gemm_split<0>, cudaFuncAttributeMaxDynamicSharedMemorySize, S_SMEM_BYTES);
    cudaFuncSetAttribute(gemm_split<3>, cudaFuncAttributeMaxDynamicSharedMemorySize, S_SMEM_BYTES);
    cudaFuncSetAttribute(gemm_split<4>, cudaFuncAttributeMaxDynamicSharedMemorySize, S_SMEM_BYTES);
    cudaFuncSetAttribute(gemm_moe<1>,   cudaFuncAttributeMaxDynamicSharedMemorySize, M_SMEM_BYTES);
    cudaFuncSetAttribute(gemm_moe<2>,   cudaFuncAttributeMaxDynamicSharedMemorySize, M_SMEM_BYTES);

    zero_counts_kernel<<<1, 32>>>();

    // operand conversions
    split_half_kernel<<<4096, 256>>>(x,  pxh,  pxl,  (long long)BT * Dm / 4);
    split_half_kernel<<<512,  256>>>(Wk, pWkh, pWkl, (long long)Dm * Dm / 4);
    split_half_kernel<<<512,  256>>>(Wv, pWvh, pWvl, (long long)Dm * Dm / 4);
    split_half_kernel<<<512,  256>>>(Wo, pWoh, pWol, (long long)Dm * Dm / 4);
    split_half_kernel<<<4096, 256>>>(fb, pfbh, pfbl, (long long)Bb * Tt * Tt / 4);
    tohalf_kernel<<<4096, 256>>>(W1, pW1h, (long long)Ee * Dm * FFd / 4);
    tohalf_kernel<<<4096, 256>>>(W2, pW2h, (long long)Ee * FFd * Dm / 4);

    // K = x@Wk + bk
    gemm_split<0><<<dim3(4, 64, 1), 512, S_SMEM_BYTES>>>(
        pxh, pxl, pWkh, pWkl, bk, pK, nullptr, nullptr, BT, Dm, Dm, 0, 0, 0, 0);
    // V = x@Wv + bv (fp32 + half-split out)
    gemm_split<3><<<dim3(4, 64, 1), 512, S_SMEM_BYTES>>>(
        pxh, pxl, pWvh, pWvl, bv, pV, pVh, pVl, BT, Dm, Dm, 0, 0, 0, 0);

    // kv_sum
    kvsum_partial_kernel<<<dim3(NCHUNK, Bb), 512>>>();
    kvsum_reduce_kernel<<<8, 256>>>();

    // wv[b] = fb[b] @ V[b] + kvsum[b] (half-split out)
    gemm_split<4><<<dim3(4, 16, Bb), 512, S_SMEM_BYTES>>>(
        pfbh, pfbl, pVh, pVl, pkvs, nullptr, pwvh, pwvl, Tt, Dm, Tt,
        (long long)Tt * Tt, (long long)Tt * Dm, Dm, (long long)Tt * Dm);

    // tmp = wv @ Wo + bo
    gemm_split<0><<<dim3(4, 64, 1), 512, S_SMEM_BYTES>>>(
        pwvh, pwvl, pWoh, pWol, bo, ptmp, nullptr, nullptr, BT, Dm, Dm, 0, 0, 0, 0);

    add_ln1_kernel<<<BT, 256>>>(x, ln1g, ln1b);
    gate_kernel<<<BT, 128>>>(Wg, bg);

    // MoE GEMM1: h = relu(x1[tok] @ W1[e] + b1[e])
    gemm_moe<1><<<dim3(16, 64, Ee), 256, M_SMEM_BYTES>>>(
        px1h, pW1h, b1, nullptr, phh, MAXTOK, FFd, Dm,
        0, (long long)Dm * FFd, FFd, (long long)MAXTOK * FFd);

    // MoE GEMM2: ybuf = w * (h @ W2[e] + b2[e])
    gemm_moe<2><<<dim3(4, 64, Ee), 256, M_SMEM_BYTES>>>(
        phh, pW2h, b2, pyb, nullptr, MAXTOK, Dm, FFd,
        (long long)MAXTOK * FFd, (long long)FFd * Dm, Dm, (long long)MAXTOK * Dm);

    combine_ln2_kernel<<<BT, 256>>>(ln2g, ln2b, out);
}

// round 17
// speedup vs baseline: 1.0390x; 1.0390x over previous
#include <cuda_runtime.h>
#include <cuda_fp16.h>
#include <mma.h>
#include <cstdint>
#include <math.h>

using namespace nvcuda;

#define Dm 512
#define Tt 2048
#define Bb 4
#define BT 8192
#define FFd 2048
#define Ee 4
#define MAXTOK 8192
#define NCHUNK 16

// ---- split GEMM (128x64 tile, BK=32, 3-stage) smem layout (halves) ----
#define ALDH 40
#define BLDH 72
#define CLD  72
#define A_STG (128 * ALDH)          // 5120
#define B_STG (32 * BLDH)           // 2304
#define ALB  (3 * A_STG)            // 15360
#define BHB  (6 * A_STG)            // 30720
#define BLB  (BHB + 3 * B_STG)      // 37632
#define S_SMEM_BYTES ((BLB + 3 * B_STG) * 2)   // 89088 B

// ---- MoE GEMM (128x128 tile, BK=32, 3-stage) smem layout ----
#define MALDH 40
#define MBLDH 136
#define MCLD  136
#define MA_STG (128 * MALDH)        // 5120
#define MB_STG (32 * MBLDH)         // 4352
#define MBHB (3 * MA_STG)           // 15360
#define M_SMEM_BYTES (128 * MCLD * 4)  // 69632 B

// ---------------- scratch ----------------
__device__ float  g_tmp[BT * Dm];
__device__ float  g_x1[BT * Dm];
__device__ float  g_part[Bb * NCHUNK * Dm];
__device__ float  g_kvsum[Bb * Dm];
__device__ float  g_bkv[2 * Dm];
__device__ int    g_counts[Ee];
__device__ int    g_tok[Ee * MAXTOK];
__device__ float  g_wslot[Ee * MAXTOK];
__device__ int    g_slottok[BT * 2];
__device__ float  g_ybuf[(size_t)Ee * MAXTOK * Dm];
// half operand buffers
__device__ __half g_xh[BT * Dm],  g_xl[BT * Dm];
__device__ __half g_Wkvh[Dm * 2 * Dm], g_Wkvl[Dm * 2 * Dm];
__device__ __half g_Woh[Dm * Dm], g_Wol[Dm * Dm];
__device__ __half g_fbh[(size_t)Bb * Tt * Tt], g_fbl[(size_t)Bb * Tt * Tt];
__device__ __half g_Kh[BT * Dm],  g_Kl[BT * Dm];
__device__ __half g_Vh[BT * Dm],  g_Vl[BT * Dm];
__device__ __half g_wvh[BT * Dm], g_wvl[BT * Dm];
__device__ __half g_x1h[BT * Dm];
__device__ __half g_W1h[(size_t)Ee * Dm * FFd];
__device__ __half g_W2h[(size_t)Ee * FFd * Dm];
__device__ __half g_hh[(size_t)Ee * MAXTOK * FFd];

// ---------------- cp.async helpers ----------------
__device__ __forceinline__ void cp_async16(uint32_t saddr, const void* gptr) {
    asm volatile("cp.async.cg.shared.global [%0], [%1], 16;" :: "r"(saddr), "l"(gptr));
}
#define CP_COMMIT() asm volatile("cp.async.commit_group;")
#define CP_WAIT(n)  asm volatile("cp.async.wait_group %0;" :: "n"(n))

__device__ __forceinline__ void split4(float4 v, __half2& h01, __half2& h23,
                                       __half2& l01, __half2& l23) {
    __half h0 = __float2half_rn(v.x), h1 = __float2half_rn(v.y);
    __half h2 = __float2half_rn(v.z), h3 = __float2half_rn(v.w);
    h01 = __halves2half2(h0, h1); h23 = __halves2half2(h2, h3);
    l01 = __halves2half2(__float2half_rn(v.x - __half2float(h0)),
                         __float2half_rn(v.y - __half2float(h1)));
    l23 = __halves2half2(__float2half_rn(v.z - __half2float(h2)),
                         __float2half_rn(v.w - __half2float(h3)));
}

// ---------------- small kernels ----------------
__global__ void zero_counts_kernel() {
    if (threadIdx.x < Ee) g_counts[threadIdx.x] = 0;
}

// fused x + fb hi/lo split
__global__ void split_xfb_kernel(const float* __restrict__ x, const float* __restrict__ fb,
                                 long long nx4, long long nfb4) {
    long long i = (long long)blockIdx.x * 256 + threadIdx.x;
    long long stride = (long long)gridDim.x * 256;
    long long total = nx4 + nfb4;
    for (; i < total; i += stride) {
        const float* src; __half *h, *l; long long j;
        if (i < nx4) { src = x;  h = g_xh;  l = g_xl;  j = i; }
        else         { src = fb; h = g_fbh; l = g_fbl; j = i - nx4; }
        float4 v = reinterpret_cast<const float4*>(src)[j];
        __half2 h01, h23, l01, l23;
        split4(v, h01, h23, l01, l23);
        reinterpret_cast<__half2*>(h)[2 * j]     = h01;
        reinterpret_cast<__half2*>(h)[2 * j + 1] = h23;
        reinterpret_cast<__half2*>(l)[2 * j]     = l01;
        reinterpret_cast<__half2*>(l)[2 * j + 1] = l23;
    }
}

// Wk|Wv concat split [Dm][2*Dm] + bias concat; plus Wo split
__global__ void prep_w_kernel(const float* __restrict__ Wk, const float* __restrict__ Wv,
                              const float* __restrict__ Wo,
                              const float* __restrict__ bk, const float* __restrict__ bv) {
    long long i = (long long)blockIdx.x * 256 + threadIdx.x;
    long long stride = (long long)gridDim.x * 256;
    const long long nkv4 = (long long)Dm * 2 * Dm / 4;   // 131072
    const long long nwo4 = (long long)Dm * Dm / 4;       // 65536
    for (; i < nkv4 + nwo4; i += stride) {
        if (i < nkv4) {
            int k = (int)(i >> 8), nc = (int)(i & 255);
            const float* src = (nc < 128) ? (Wk + (long long)k * Dm + nc * 4)
                                          : (Wv + (long long)k * Dm + (nc - 128) * 4);
            float4 v = *reinterpret_cast<const float4*>(src);
            __half2 h01, h23, l01, l23;
            split4(v, h01, h23, l01, l23);
            long long o = (long long)k * (2 * Dm) + nc * 4;
            reinterpret_cast<__half2*>(g_Wkvh + o)[0] = h01;
            reinterpret_cast<__half2*>(g_Wkvh + o)[1] = h23;
            reinterpret_cast<__half2*>(g_Wkvl + o)[0] = l01;
            reinterpret_cast<__half2*>(g_Wkvl + o)[1] = l23;
        } else {
            long long j = i - nkv4;
            float4 v = reinterpret_cast<const float4*>(Wo)[j];
            __half2 h01, h23, l01, l23;
            split4(v, h01, h23, l01, l23);
            reinterpret_cast<__half2*>(g_Woh)[2 * j]     = h01;
            reinterpret_cast<__half2*>(g_Woh)[2 * j + 1] = h23;
            reinterpret_cast<__half2*>(g_Wol)[2 * j]     = l01;
            reinterpret_cast<__half2*>(g_Wol)[2 * j + 1] = l23;
        }
    }
    if (blockIdx.x == 0 && threadIdx.x < 2 * Dm / 4) {
        int n = threadIdx.x * 4;
        float4 v = (n < Dm) ? *reinterpret_cast<const float4*>(bk + n)
                            : *reinterpret_cast<const float4*>(bv + n - Dm);
        *reinterpret_cast<float4*>(g_bkv + n) = v;
    }
}

// fused W1+W2 -> half
__global__ void tohalf_w12_kernel(const float* __restrict__ W1, const float* __restrict__ W2,
                                  long long n14, long long n24) {
    long long i = (long long)blockIdx.x * 256 + threadIdx.x;
    long long stride = (long long)gridDim.x * 256;
    for (; i < n14 + n24; i += stride) {
        const float* src; __half* h; long long j;
        if (i < n14) { src = W1; h = g_W1h; j = i; }
        else         { src = W2; h = g_W2h; j = i - n14; }
        float4 v = reinterpret_cast<const float4*>(src)[j];
        reinterpret_cast<__half2*>(h)[2 * j]     = __halves2half2(__float2half_rn(v.x), __float2half_rn(v.y));
        reinterpret_cast<__half2*>(h)[2 * j + 1] = __halves2half2(__float2half_rn(v.z), __float2half_rn(v.w));
    }
}

// kvsum from half-split K,V
__global__ void kvsum_partial_kernel() {
    int b = blockIdx.y, tc = blockIdx.x, d = threadIdx.x;
    long long base = ((long long)b * Tt + (long long)tc * (Tt / NCHUNK)) * Dm;
    float s = 0.f;
#pragma unroll 8
    for (int t = 0; t < Tt / NCHUNK; ++t) {
        long long o = base + (long long)t * Dm + d;
        float kk = __half2float(g_Kh[o]) + __half2float(g_Kl[o]);
        float vv = __half2float(g_Vh[o]) + __half2float(g_Vl[o]);
        s += kk * vv;
    }
    g_part[((long long)b * NCHUNK + tc) * Dm + d] = s;
}
__global__ void kvsum_reduce_kernel() {
    int i = blockIdx.x * 256 + threadIdx.x;
    int b = i >> 9;
    float s = 0.f;
    for (int tc = 0; tc < NCHUNK; ++tc)
        s += g_part[((long long)b * NCHUNK + tc) * Dm + (i & 511)];
    g_kvsum[i] = s;
}

// ---------------- split fp16 GEMM (128x64, BK=32, 3-stage) ----------------
// MODE 0: fp32 out (Wo); MODE 4: half-split out (fbV); MODE 5: KV combined (N=1024,
//   col<512 -> K half-split, col>=512 -> V half-split, both at row stride 512)
template<int MODE>
__global__ __launch_bounds__(256, 2)
void gemm_split(const __half* __restrict__ Ahg, const __half* __restrict__ Alg,
                const __half* __restrict__ Bhg, const __half* __restrict__ Blg,
                const float* __restrict__ bias,
                float* __restrict__ Cf, __half* __restrict__ Chh, __half* __restrict__ Chl,
                __half* __restrict__ C2h, __half* __restrict__ C2l,
                int M, int N, int K,
                long long sA, long long sB, long long sBias, long long sC)
{
    extern __shared__ __half smh[];
    const int z = blockIdx.z;
    const int row0 = blockIdx.y * 128;
    const int col0 = blockIdx.x * 64;
    Ahg += (long long)z * sA;  Alg += (long long)z * sA;
    Bhg += (long long)z * sB;  Blg += (long long)z * sB;
    const float* bz = bias + (long long)z * sBias;
    const long long coff = (long long)z * sC;

    const int tid = threadIdx.x;
    const int warpId = tid >> 5;
    const int warpM = warpId >> 1;
    const int warpN = warpId & 1;

    const uint32_t sbase = (uint32_t)__cvta_generic_to_shared(smh);

#define LOAD_TILE(stage, kk)                                                      \
    do {                                                                          \
        _Pragma("unroll")                                                         \
        for (int p = 0; p < 2; p++) {                                             \
            int c = tid + p * 256;                                                \
            int r = c >> 2, c8 = (c & 3) * 8;                                     \
            cp_async16(sbase + ((stage) * A_STG + r * ALDH + c8) * 2,             \
                       Ahg + (long long)(row0 + r) * K + (kk) + c8);              \
            cp_async16(sbase + (ALB + (stage) * A_STG + r * ALDH + c8) * 2,       \
                       Alg + (long long)(row0 + r) * K + (kk) + c8);              \
        }                                                                         \
        {                                                                         \
            int r = tid >> 3, c8 = (tid & 7) * 8;                                 \
            cp_async16(sbase + (BHB + (stage) * B_STG + r * BLDH + c8) * 2,       \
                       Bhg + (long long)((kk) + r) * N + col0 + c8);              \
            cp_async16(sbase + (BLB + (stage) * B_STG + r * BLDH + c8) * 2,       \
                       Blg + (long long)((kk) + r) * N + col0 + c8);              \
        }                                                                         \
    } while (0)

    wmma::fragment<wmma::accumulator, 16, 16, 16, float> acc[2][2];
#pragma unroll
    for (int i = 0; i < 2; i++)
#pragma unroll
        for (int j = 0; j < 2; j++) wmma::fill_fragment(acc[i][j], 0.f);

    const int nk = K >> 5;
    LOAD_TILE(0, 0); CP_COMMIT();
    LOAD_TILE(1, 32); CP_COMMIT();

    int s = 0;
    for (int t = 0; t < nk; ++t) {
        if (t + 2 < nk) {
            int s2 = s + 2; if (s2 >= 3) s2 -= 3;
            LOAD_TILE(s2, (t + 2) * 32);
            CP_COMMIT();
            CP_WAIT(2);
        } else if (t + 1 < nk) {
            CP_WAIT(1);
        } else {
            CP_WAIT(0);
        }
        __syncthreads();

        const __half* As_h = smh + s * A_STG;
        const __half* As_l = smh + ALB + s * A_STG;
        const __half* Bs_h = smh + BHB + s * B_STG;
        const __half* Bs_l = smh + BLB + s * B_STG;
#pragma unroll
        for (int ks = 0; ks < 2; ks++) {
            wmma::fragment<wmma::matrix_a, 16, 16, 16, __half, wmma::row_major> ah[2], al[2];
#pragma unroll
            for (int i = 0; i < 2; i++) {
                wmma::load_matrix_sync(ah[i], As_h + (warpM * 32 + i * 16) * ALDH + ks * 16, ALDH);
                wmma::load_matrix_sync(al[i], As_l + (warpM * 32 + i * 16) * ALDH + ks * 16, ALDH);
            }
#pragma unroll
            for (int j = 0; j < 2; j++) {
                wmma::fragment<wmma::matrix_b, 16, 16, 16, __half, wmma::row_major> bh, bl;
                wmma::load_matrix_sync(bh, Bs_h + (ks * 16) * BLDH + warpN * 32 + j * 16, BLDH);
                wmma::load_matrix_sync(bl, Bs_l + (ks * 16) * BLDH + warpN * 32 + j * 16, BLDH);
#pragma unroll
                for (int i = 0; i < 2; i++) {
                    wmma::mma_sync(acc[i][j], ah[i], bh, acc[i][j]);
                    wmma::mma_sync(acc[i][j], ah[i], bl, acc[i][j]);
                    wmma::mma_sync(acc[i][j], al[i], bh, acc[i][j]);
                }
            }
        }
        __syncthreads();
        s = (s == 2) ? 0 : s + 1;
    }
#undef LOAD_TILE

    float* Cbuf = reinterpret_cast<float*>(smh);
#pragma unroll
    for (int i = 0; i < 2; i++)
#pragma unroll
        for (int j = 0; j < 2; j++)
            wmma::store_matrix_sync(Cbuf + (warpM * 32 + i * 16) * CLD + warpN * 32 + j * 16,
                                    acc[i][j], CLD, wmma::mem_row_major);
    __syncthreads();

#pragma unroll
    for (int it = 0; it < 8; it++) {
        int f = tid + it * 256;
        int r = f >> 4, c4 = f & 15;
        int grow = row0 + r;
        float4 v = *reinterpret_cast<const float4*>(Cbuf + r * CLD + c4 * 4);
        int col = col0 + c4 * 4;
        v.x += __ldg(bz + col + 0);
        v.y += __ldg(bz + col + 1);
        v.z += __ldg(bz + col + 2);
        v.w += __ldg(bz + col + 3);
        if (MODE == 0) {
            *reinterpret_cast<float4*>(Cf + coff + (long long)grow * N + col) = v;
        } else if (MODE == 4) {
            long long idx = coff + (long long)grow * N + col;
            __half2 h01, h23, l01, l23;
            split4(v, h01, h23, l01, l23);
            *reinterpret_cast<__half2*>(Chh + idx)     = h01;
            *reinterpret_cast<__half2*>(Chh + idx + 2) = h23;
            *reinterpret_cast<__half2*>(Chl + idx)     = l01;
            *reinterpret_cast<__half2*>(Chl + idx + 2) = l23;
        } else {  // MODE 5: KV combined
            __half2 h01, h23, l01, l23;
            split4(v, h01, h23, l01, l23);
            __half *dh, *dl; long long idx;
            if (col < Dm) { dh = Chh; dl = Chl; idx = (long long)grow * Dm + col; }
            else          { dh = C2h; dl = C2l; idx = (long long)grow * Dm + col - Dm; }
            *reinterpret_cast<__half2*>(dh + idx)     = h01;
            *reinterpret_cast<__half2*>(dh + idx + 2) = h23;
            *reinterpret_cast<__half2*>(dl + idx)     = l01;
            *reinterpret_cast<__half2*>(dl + idx + 2) = l23;
        }
    }
}

// ---------------- MoE fp16 GEMM (128x128, BK=32, 3-stage) ----------------
template<int MODE>
__global__ __launch_bounds__(256, 2)
void gemm_moe(const __half* __restrict__ Ag, const __half* __restrict__ Bg,
              const float* __restrict__ bias,
              float* __restrict__ Cf, __half* __restrict__ Ch,
              int M, int N, int K,
              long long sA, long long sB, long long sBias, long long sC)
{
    extern __shared__ __half smh[];
    const int z = blockIdx.z;
    const int cnt = g_counts[z];
    const int row0 = blockIdx.y * 128;
    if (row0 >= cnt) return;
    const int col0 = blockIdx.x * 128;
    Ag += (long long)z * sA;
    Bg += (long long)z * sB;
    const float* bz = bias + (long long)z * sBias;
    const long long coff = (long long)z * sC;

    const int tid = threadIdx.x;
    const int warpId = tid >> 5;
    const int warpM = warpId >> 1;
    const int warpN = warpId & 1;

    __shared__ int toks[128];
    if (MODE == 1 && tid < 128) {
        int slot = row0 + tid;
        toks[tid] = (slot < cnt) ? g_tok[z * MAXTOK + slot] : g_tok[z * MAXTOK];
    }
    if (MODE == 1) __syncthreads();

    const uint32_t sbase = (uint32_t)__cvta_generic_to_shared(smh);

#define MLOAD(stage, kk)                                                          \
    do {                                                                          \
        _Pragma("unroll")                                                         \
        for (int p = 0; p < 2; p++) {                                             \
            int c = tid + p * 256;                                                \
            int r = c >> 2, c8 = (c & 3) * 8;                                     \
            int rowIdx = (MODE == 1) ? toks[r] : (row0 + r);                      \
            cp_async16(sbase + ((stage) * MA_STG + r * MALDH + c8) * 2,           \
                       Ag + (long long)rowIdx * K + (kk) + c8);                   \
        }                                                                         \
        _Pragma("unroll")                                                         \
        for (int p = 0; p < 2; p++) {                                             \
            int c = tid + p * 256;                                                \
            int r = c >> 4, c8 = (c & 15) * 8;                                    \
            cp_async16(sbase + (MBHB + (stage) * MB_STG + r * MBLDH + c8) * 2,    \
                       Bg + (long long)((kk) + r) * N + col0 + c8);               \
        }                                                                         \
    } while (0)

    wmma::fragment<wmma::accumulator, 16, 16, 16, float> acc[2][4];
#pragma unroll
    for (int i = 0; i < 2; i++)
#pragma unroll
        for (int j = 0; j < 4; j++) wmma::fill_fragment(acc[i][j], 0.f);

    const int nk = K >> 5;
    MLOAD(0, 0); CP_COMMIT();
    MLOAD(1, 32); CP_COMMIT();

    int s = 0;
    for (int t = 0; t < nk; ++t) {
        if (t + 2 < nk) {
            int s2 = s + 2; if (s2 >= 3) s2 -= 3;
            MLOAD(s2, (t + 2) * 32);
            CP_COMMIT();
            CP_WAIT(2);
        } else if (t + 1 < nk) {
            CP_WAIT(1);
        } else {
            CP_WAIT(0);
        }
        __syncthreads();

        const __half* As = smh + s * MA_STG;
        const __half* Bs = smh + MBHB + s * MB_STG;
#pragma unroll
        for (int ks = 0; ks < 2; ks++) {
            wmma::fragment<wmma::matrix_a, 16, 16, 16, __half, wmma::row_major> ah[2];
#pragma unroll
            for (int i = 0; i < 2; i++)
                wmma::load_matrix_sync(ah[i], As + (warpM * 32 + i * 16) * MALDH + ks * 16, MALDH);
#pragma unroll
            for (int j = 0; j < 4; j++) {
                wmma::fragment<wmma::matrix_b, 16, 16, 16, __half, wmma::row_major> bh;
                wmma::load_matrix_sync(bh, Bs + (ks * 16) * MBLDH + warpN * 64 + j * 16, MBLDH);
#pragma unroll
                for (int i = 0; i < 2; i++)
                    wmma::mma_sync(acc[i][j], ah[i], bh, acc[i][j]);
            }
        }
        __syncthreads();
        s = (s == 2) ? 0 : s + 1;
    }
#undef MLOAD

    float* Cbuf = reinterpret_cast<float*>(smh);
#pragma unroll
    for (int i = 0; i < 2; i++)
#pragma unroll
        for (int j = 0; j < 4; j++)
            wmma::store_matrix_sync(Cbuf + (warpM * 32 + i * 16) * MCLD + warpN * 64 + j * 16,
                                    acc[i][j], MCLD, wmma::mem_row_major);
    __syncthreads();

#pragma unroll
    for (int it = 0; it < 16; it++) {
        int f = tid + it * 256;
        int r = f >> 5, c4 = f & 31;
        int grow = row0 + r;
        if (grow >= cnt) continue;
        float4 v = *reinterpret_cast<const float4*>(Cbuf + r * MCLD + c4 * 4);
        int col = col0 + c4 * 4;
        v.x += __ldg(bz + col + 0);
        v.y += __ldg(bz + col + 1);
        v.z += __ldg(bz + col + 2);
        v.w += __ldg(bz + col + 3);
        long long idx = coff + (long long)grow * N + col;
        if (MODE == 1) {
            v.x = fmaxf(v.x, 0.f); v.y = fmaxf(v.y, 0.f);
            v.z = fmaxf(v.z, 0.f); v.w = fmaxf(v.w, 0.f);
            *reinterpret_cast<__half2*>(Ch + idx)     = __halves2half2(__float2half_rn(v.x), __float2half_rn(v.y));
            *reinterpret_cast<__half2*>(Ch + idx + 2) = __halves2half2(__float2half_rn(v.z), __float2half_rn(v.w));
        } else {
            float w = g_wslot[z * MAXTOK + grow];
            v.x *= w; v.y *= w; v.z *= w; v.w *= w;
            *reinterpret_cast<float4*>(Cf + idx) = v;
        }
    }
}

// ---------------- fused LN1 + gate ----------------
__global__ __launch_bounds__(256) void ln1_gate_kernel(
    const float* __restrict__ x, const float* __restrict__ g, const float* __restrict__ b,
    const float* __restrict__ Wg, const float* __restrict__ bg)
{
    int t = blockIdx.x, tid = threadIdx.x;
    const float* xr = x + (long long)t * Dm;
    const float* tr = g_tmp + (long long)t * Dm;
    float v0 = xr[tid] + tr[tid];
    float v1 = xr[tid + 256] + tr[tid + 256];
    __shared__ float red[256];
    __shared__ float smr[4][256];
    red[tid] = v0 + v1;
    __syncthreads();
    for (int off = 128; off; off >>= 1) { if (tid < off) red[tid] += red[tid + off]; __syncthreads(); }
    float mu = red[0] * (1.0f / 512.0f);
    __syncthreads();
    float d0 = v0 - mu, d1 = v1 - mu;
    red[tid] = d0 * d0 + d1 * d1;
    __syncthreads();
    for (int off = 128; off; off >>= 1) { if (tid < off) red[tid] += red[tid + off]; __syncthreads(); }
    float inv = rsqrtf(red[0] * (1.0f / 512.0f) + 1e-5f);
    float o0 = d0 * inv * g[tid] + b[tid];
    float o1 = d1 * inv * g[tid + 256] + b[tid + 256];
    g_x1[(long long)t * Dm + tid]        = o0;
    g_x1[(long long)t * Dm + tid + 256]  = o1;
    g_x1h[(long long)t * Dm + tid]       = __float2half_rn(o0);
    g_x1h[(long long)t * Dm + tid + 256] = __float2half_rn(o1);

    // gate logits from in-register fp32 x1
    float4 w0 = reinterpret_cast<const float4*>(Wg)[tid];
    float4 w1 = reinterpret_cast<const float4*>(Wg)[tid + 256];
    smr[0][tid] = o0 * w0.x + o1 * w1.x;
    smr[1][tid] = o0 * w0.y + o1 * w1.y;
    smr[2][tid] = o0 * w0.z + o1 * w1.z;
    smr[3][tid] = o0 * w0.w + o1 * w1.w;
    __syncthreads();
    for (int off = 128; off; off >>= 1) {
        if (tid < off) {
            smr[0][tid] += smr[0][tid + off];
            smr[1][tid] += smr[1][tid + off];
            smr[2][tid] += smr[2][tid + off];
            smr[3][tid] += smr[3][tid + off];
        }
        __syncthreads();
    }
    if (tid == 0) {
        float s[4] = { smr[0][0] + bg[0], smr[1][0] + bg[1], smr[2][0] + bg[2], smr[3][0] + bg[3] };
        float m = fmaxf(fmaxf(s[0], s[1]), fmaxf(s[2], s[3]));
        float ex[4]; float sum = 0.f;
        for (int e = 0; e < 4; e++) { ex[e] = expf(s[e] - m); sum += ex[e]; }
        float invs = 1.0f / sum;
        float pr[4];
        for (int e = 0; e < 4; e++) pr[e] = ex[e] * invs;
        int i0 = 0;
        for (int e = 1; e < 4; e++) if (pr[e] > pr[i0]) i0 = e;
        int i1 = -1;
        for (int e = 0; e < 4; e++) {
            if (e == i0) continue;
            if (i1 < 0 || pr[e] > pr[i1]) i1 = e;
        }
        int s0 = atomicAdd(&g_counts[i0], 1);
        g_tok[i0 * MAXTOK + s0] = t;
        g_wslot[i0 * MAXTOK + s0] = pr[i0];
        g_slottok[2 * t] = i0 * MAXTOK + s0;
        int s1 = atomicAdd(&g_counts[i1], 1);
        g_tok[i1 * MAXTOK + s1] = t;
        g_wslot[i1 * MAXTOK + s1] = pr[i1];
        g_slottok[2 * t + 1] = i1 * MAXTOK + s1;
    }
}

// ---------------- combine + LN2 ----------------
__global__ __launch_bounds__(256) void combine_ln2_kernel(
    const float* __restrict__ g, const float* __restrict__ b, float* __restrict__ out)
{
    int t = blockIdx.x, tid = threadIdx.x;
    int s0 = g_slottok[2 * t], s1 = g_slottok[2 * t + 1];
    const float* xr = g_x1 + (long long)t * Dm;
    const float* y0 = g_ybuf + (long long)s0 * Dm;
    const float* y1 = g_ybuf + (long long)s1 * Dm;
    float v0 = xr[tid] + y0[tid] + y1[tid];
    float v1 = xr[tid + 256] + y0[tid + 256] + y1[tid + 256];
    __shared__ float red[256];
    red[tid] = v0 + v1;
    __syncthreads();
    for (int off = 128; off; off >>= 1) { if (tid < off) red[tid] += red[tid + off]; __syncthreads(); }
    float mu = red[0] * (1.0f / 512.0f);
    __syncthreads();
    float d0 = v0 - mu, d1 = v1 - mu;
    red[tid] = d0 * d0 + d1 * d1;
    __syncthreads();
    for (int off = 128; off; off >>= 1) { if (tid < off) red[tid] += red[tid + off]; __syncthreads(); }
    float inv = rsqrtf(red[0] * (1.0f / 512.0f) + 1e-5f);
    out[(long long)t * Dm + tid]       = d0 * inv * g[tid] + b[tid];
    out[(long long)t * Dm + tid + 256] = d1 * inv * g[tid + 256] + b[tid + 256];
}

// ---------------- launch ----------------
extern "C" void kernel_launch(void* const* d_in, const int* in_sizes, int n_in,
                              void* d_out, int out_size)
{
    const float* x    = (const float*)d_in[0];
    const float* fb   = (const float*)d_in[1];
    const float* Wk   = (const float*)d_in[2];
    const float* bk   = (const float*)d_in[3];
    const float* Wv   = (const float*)d_in[4];
    const float* bv   = (const float*)d_in[5];
    const float* Wo   = (const float*)d_in[6];
    const float* bo   = (const float*)d_in[7];
    const float* ln1g = (const float*)d_in[8];
    const float* ln1b = (const float*)d_in[9];
    const float* Wg   = (const float*)d_in[10];
    const float* bg   = (const float*)d_in[11];
    const float* W1   = (const float*)d_in[12];
    const float* b1   = (const float*)d_in[13];
    const float* W2   = (const float*)d_in[14];
    const float* b2   = (const float*)d_in[15];
    const float* ln2g = (const float*)d_in[16];
    const float* ln2b = (const float*)d_in[17];
    float* out = (float*)d_out;

    float *ptmp, *pkvs, *pyb, *pbkv;
    __half *pxh, *pxl, *pWkvh, *pWkvl, *pWoh, *pWol;
    __half *pfbh, *pfbl, *pKh, *pKl, *pVh, *pVl, *pwvh, *pwvl, *px1h, *pW1h, *pW2h, *phh;
    cudaGetSymbolAddress((void**)&ptmp, g_tmp);
    cudaGetSymbolAddress((void**)&pkvs, g_kvsum);
    cudaGetSymbolAddress((void**)&pyb,  g_ybuf);
    cudaGetSymbolAddress((void**)&pbkv, g_bkv);
    cudaGetSymbolAddress((void**)&pxh,  g_xh);
    cudaGetSymbolAddress((void**)&pxl,  g_xl);
    cudaGetSymbolAddress((void**)&pWkvh, g_Wkvh);
    cudaGetSymbolAddress((void**)&pWkvl, g_Wkvl);
    cudaGetSymbolAddress((void**)&pWoh, g_Woh);
    cudaGetSymbolAddress((void**)&pWol, g_Wol);
    cudaGetSymbolAddress((void**)&pfbh, g_fbh);
    cudaGetSymbolAddress((void**)&pfbl, g_fbl);
    cudaGetSymbolAddress((void**)&pKh,  g_Kh);
    cudaGetSymbolAddress((void**)&pKl,  g_Kl);
    cudaGetSymbolAddress((void**)&pVh,  g_Vh);
    cudaGetSymbolAddress((void**)&pVl,  g_Vl);
    cudaGetSymbolAddress((void**)&pwvh, g_wvh);
    cudaGetSymbolAddress((void**)&pwvl, g_wvl);
    cudaGetSymbolAddress((void**)&px1h, g_x1h);
    cudaGetSymbolAddress((void**)&pW1h, g_W1h);
    cudaGetSymbolAddress((void**)&pW2h, g_W2h);
    cudaGetSymbolAddress((void**)&phh,  g_hh);

    cudaFuncSetAttribute(gemm_split<0>, cudaFuncAttributeMaxDynamicSharedMemorySize, S_SMEM_BYTES);
    cudaFuncSetAttribute(gemm_split<4>, cudaFuncAttributeMaxDynamicSharedMemorySize, S_SMEM_BYTES);
    cudaFuncSetAttribute(gemm_split<5>, cudaFuncAttributeMaxDynamicSharedMemorySize, S_SMEM_BYTES);
    cudaFuncSetAttribute(gemm_moe<1>,   cudaFuncAttributeMaxDynamicSharedMemorySize, M_SMEM_BYTES);
    cudaFuncSetAttribute(gemm_moe<2>,   cudaFuncAttributeMaxDynamicSharedMemorySize, M_SMEM_BYTES);

    zero_counts_kernel<<<1, 32>>>();

    // fused operand conversions
    split_xfb_kernel<<<4096, 256>>>(x, fb, (long long)BT * Dm / 4, (long long)Bb * Tt * Tt / 4);
    prep_w_kernel<<<768, 256>>>(Wk, Wv, Wo, bk, bv);
    tohalf_w12_kernel<<<4096, 256>>>(W1, W2, (long long)Ee * Dm * FFd / 4, (long long)Ee * FFd * Dm / 4);

    // K|V = x @ (Wk|Wv) + (bk|bv)  -> half-split K and V
    gemm_split<5><<<dim3(16, 64, 1), 256, S_SMEM_BYTES>>>(
        pxh, pxl, pWkvh, pWkvl, pbkv, nullptr, pKh, pKl, pVh, pVl,
        BT, 2 * Dm, Dm, 0, 0, 0, 0);

    // kv_sum (deterministic two-stage, from half-split K,V)
    kvsum_partial_kernel<<<dim3(NCHUNK, Bb), 512>>>();
    kvsum_reduce_kernel<<<8, 256>>>();

    // wv[b] = fb[b] @ V[b] + kvsum[b] (half-split out)
    gemm_split<4><<<dim3(8, 16, Bb), 256, S_SMEM_BYTES>>>(
        pfbh, pfbl, pVh, pVl, pkvs, nullptr, pwvh, pwvl, nullptr, nullptr,
        Tt, Dm, Tt, (long long)Tt * Tt, (long long)Tt * Dm, Dm, (long long)Tt * Dm);

    // tmp = wv @ Wo + bo (fp32 out)
    gemm_split<0><<<dim3(8, 64, 1), 256, S_SMEM_BYTES>>>(
        pwvh, pwvl, pWoh, pWol, bo, ptmp, nullptr, nullptr, nullptr, nullptr,
        BT, Dm, Dm, 0, 0, 0, 0);

    // fused LN1 + gate
    ln1_gate_kernel<<<BT, 256>>>(x, ln1g, ln1b, Wg, bg);

    // MoE GEMM1: h = relu(x1[tok] @ W1[e] + b1[e])
    gemm_moe<1><<<dim3(16, 64, Ee), 256, M_SMEM_BYTES>>>(
        px1h, pW1h, b1, nullptr, phh, MAXTOK, FFd, Dm,
        0, (long long)Dm * FFd, FFd, (long long)MAXTOK * FFd);

    // MoE GEMM2: ybuf = w * (h @ W2[e] + b2[e])
    gemm_moe<2><<<dim3(4, 64, Ee), 256, M_SMEM_BYTES>>>(
        phh, pW2h, b2, pyb, nullptr, MAXTOK, Dm, FFd,
        (long long)MAXTOK * FFd, (long long)FFd * Dm, Dm, (long long)MAXTOK * Dm);

    combine_ln2_kernel<<<BT, 256>>>(ln2g, ln2b, out);
}